// round 16
// baseline (speedup 1.0000x reference)
#include <cuda_runtime.h>
#include <math_constants.h>
#include <cstdint>

// 5x5 per-channel max (cv2.dilate), SAME padding, (64,384,384,3) fp32.
// Fused dim L = W*C = 1152 floats; 144 8-word blocks per row.
// R16: bulk-async (cp.async.bulk, 1-D, no tensor map) producer/consumer
// pipeline. Double-buffered smem strip (20 in-rows, guard-padded rows);
// producer warp streams rows with mbarrier expect_tx; 20 consumer warps
// (4 groups x 5-warp full-row teams, 4 output rows each) run the champion
// math from smem: 5-ring vertical max (LDS.128) + 12-shuffle hmax8.
// 2 mbarrier waits per strip. Persistent grid 140, 672 threads, 1 block/SM.

#define B_     64
#define H_     384
#define L_     1152
#define L4_    288
#define ROWB   4608            // gmem bytes per fused row
#define SROWB  4672            // smem row: 32B guard + 4608 + 32B guard
#define TY     16
#define SPB    24              // strips per batch (24*16 = 384)
#define NSTR   (B_ * SPB)      // 1536
#define INR    20              // in-rows per strip (TY + 4)
#define BUFB   (INR * SROWB)   // 93440
#define SMOFF  128
#define SMEMB  (SMOFF + 2 * BUFB)   // 187008
#define NT     672             // 21 warps: 20 consumers + 1 producer
#define NCONS  640
#define GRID   140
#define TXB    (INR * ROWB)    // 92160
#define FULLM  0xffffffffu

__device__ __forceinline__ float4 f4max(float4 a, float4 b) {
    return make_float4(fmaxf(a.x, b.x), fmaxf(a.y, b.y),
                       fmaxf(a.z, b.z), fmaxf(a.w, b.w));
}

// horizontal 5-max over 8 fused words using lane+-1 shuffles (stride-3 trick)
__device__ __forceinline__ void hmax8(const float4 mA, const float4 mB,
                                      float4& oA, float4& oB)
{
    const float v0 = mA.x, v1 = mA.y, v2 = mA.z, v3 = mA.w;
    const float v4 = mB.x, v5 = mB.y, v6 = mB.z, v7 = mB.w;

    const float l0 = __shfl_up_sync(FULLM, v2, 1);
    const float l1 = __shfl_up_sync(FULLM, v3, 1);
    const float l2 = __shfl_up_sync(FULLM, v4, 1);
    const float l3 = __shfl_up_sync(FULLM, v5, 1);
    const float l4 = __shfl_up_sync(FULLM, v6, 1);
    const float l5 = __shfl_up_sync(FULLM, v7, 1);
    const float r0 = __shfl_down_sync(FULLM, v0, 1);
    const float r1 = __shfl_down_sync(FULLM, v1, 1);
    const float r2 = __shfl_down_sync(FULLM, v2, 1);
    const float r3 = __shfl_down_sync(FULLM, v3, 1);
    const float r4 = __shfl_down_sync(FULLM, v4, 1);
    const float r5 = __shfl_down_sync(FULLM, v5, 1);

    const float m3_m6 = fmaxf(l0, l3);
    const float m3_m5 = fmaxf(l1, l4);
    const float m3_m4 = fmaxf(l2, l5);
    const float m3_m3 = fmaxf(l3, v0);
    const float m3_m2 = fmaxf(l4, v1);
    const float m3_m1 = fmaxf(l5, v2);
    const float m3_0  = fmaxf(v0, v3);
    const float m3_1  = fmaxf(v1, v4);
    const float m3_2  = fmaxf(v2, v5);
    const float m3_3  = fmaxf(v3, v6);
    const float m3_4  = fmaxf(v4, v7);
    const float m3_5  = fmaxf(v5, r0);
    const float m3_6  = fmaxf(v6, r1);
    const float m3_7  = fmaxf(v7, r2);

    oA.x = fmaxf(m3_m6, fmaxf(m3_0, v6));
    oA.y = fmaxf(m3_m5, fmaxf(m3_1, v7));
    oA.z = fmaxf(m3_m4, fmaxf(m3_2, r0));
    oA.w = fmaxf(m3_m3, fmaxf(m3_3, r1));
    oB.x = fmaxf(m3_m2, fmaxf(m3_4, r2));
    oB.y = fmaxf(m3_m1, fmaxf(m3_5, r3));
    oB.z = fmaxf(m3_0,  fmaxf(m3_6, r4));
    oB.w = fmaxf(m3_1,  fmaxf(m3_7, r5));
}

// ---- mbarrier / bulk-async primitives ----
__device__ __forceinline__ void mbar_init(unsigned a, unsigned cnt) {
    asm volatile("mbarrier.init.shared.b64 [%0], %1;" :: "r"(a), "r"(cnt) : "memory");
}
__device__ __forceinline__ void mbar_expect_tx(unsigned a, unsigned bytes) {
    asm volatile("mbarrier.arrive.expect_tx.shared.b64 _, [%0], %1;"
                 :: "r"(a), "r"(bytes) : "memory");
}
__device__ __forceinline__ void mbar_arrive(unsigned a) {
    asm volatile("mbarrier.arrive.shared.b64 _, [%0];" :: "r"(a) : "memory");
}
__device__ __forceinline__ void mbar_wait(unsigned a, int parity) {
    asm volatile(
        "{\n\t.reg .pred P;\n\t"
        "WL_%=:\n\t"
        "mbarrier.try_wait.parity.acquire.cta.shared::cta.b64 P, [%0], %1, 0x989680;\n\t"
        "@P bra.uni WD_%=;\n\t"
        "bra.uni WL_%=;\n\t"
        "WD_%=:\n\t}"
        :: "r"(a), "r"((unsigned)parity) : "memory");
}
__device__ __forceinline__ void mbar_wait_relaxed(unsigned a, int parity) {
    asm volatile(
        "{\n\t.reg .pred P;\n\t"
        "WL_%=:\n\t"
        "mbarrier.try_wait.parity.relaxed.cta.shared::cta.b64 P, [%0], %1, 0x989680;\n\t"
        "@P bra.uni WD_%=;\n\t"
        "bra.uni WL_%=;\n\t"
        "WD_%=:\n\t}"
        :: "r"(a), "r"((unsigned)parity) : "memory");
}
__device__ __forceinline__ void bulk_cp(unsigned dst, const void* src,
                                        unsigned bytes, unsigned mbar) {
    asm volatile(
        "cp.async.bulk.shared::cluster.global.mbarrier::complete_tx::bytes "
        "[%0], [%1], %2, [%3];"
        :: "r"(dst), "l"(src), "r"(bytes), "r"(mbar) : "memory");
}

__global__ __launch_bounds__(NT, 1)
void dilate5_kernel(const float* __restrict__ in,
                    const int* __restrict__ kptr,
                    float* __restrict__ out)
{
    extern __shared__ char smem[];
    const int k   = *kptr;
    const int t   = threadIdx.x;
    const int wid = t >> 5;
    const int l   = t & 31;
    const unsigned sbase = (unsigned)__cvta_generic_to_shared(smem);
    // barriers: [full0, full1, empty0, empty1] at 0,8,16,24
    const unsigned FB = sbase;
    const unsigned EB = sbase + 16;

    if (k == 5) {
        // ---- init: barriers + -inf guard columns (written once) ----
        if (t == 0) {
            mbar_init(FB + 0, 1);      mbar_init(FB + 8, 1);
            mbar_init(EB + 0, NCONS);  mbar_init(EB + 8, NCONS);
        }
        for (int i = t; i < 2 * INR; i += NT) {
            char* row = smem + SMOFF + (i / INR) * BUFB + (i % INR) * SROWB;
            float* gl = (float*)row;                 // left guard: 8 words
            float* gr = (float*)(row + 32 + ROWB);   // right guard: 8 words
            #pragma unroll
            for (int j = 0; j < 8; ++j) { gl[j] = -CUDART_INF_F; gr[j] = -CUDART_INF_F; }
        }
        __syncthreads();

        if (wid == 20) {
            // ---------------- producer warp (one thread) ----------------
            if (l == 0) {
                int ph[2] = {1, 1};                  // first empty-wait passes
                int cnt = 0;
                for (int sid = blockIdx.x; sid < NSTR; sid += GRID, ++cnt) {
                    const int buf = cnt & 1;
                    mbar_wait_relaxed(EB + 8u * buf, ph[buf]);
                    ph[buf] ^= 1;
                    mbar_expect_tx(FB + 8u * buf, TXB);

                    const int b  = sid / SPB;
                    const int y0 = (sid % SPB) * TY;
                    const char* gsrc = (const char*)(in + (size_t)b * H_ * L_);
                    const unsigned d0 = sbase + SMOFF + (unsigned)buf * BUFB + 32u;
                    #pragma unroll
                    for (int j = 0; j < INR; ++j) {
                        int y = y0 - 2 + j;
                        y = (y < 0) ? 0 : ((y > H_ - 1) ? H_ - 1 : y);  // clamp pad
                        bulk_cp(d0 + (unsigned)j * SROWB,
                                gsrc + (size_t)y * ROWB, ROWB, FB + 8u * buf);
                    }
                }
            }
        } else {
            // ---------------- consumer warps (4 groups x 5 warps) ----------------
            const int g  = wid / 5;              // 0..3 -> rows 4g..4g+3
            const int wg = wid % 5;
            const int o  = 30 * wg + l - 1;      // 8-word block (-1..150)
            const bool ld_ok = (o <= 144);       // o==144/-1 hit guards (-inf)
            const bool st_ok = (l >= 1) && (l <= 30) && (o >= 0) && (o < 144);
            const int boff   = 32 + o * 32;      // byte offset in padded row
            const float NI   = -CUDART_INF_F;
            const float4 NEG4 = make_float4(NI, NI, NI, NI);
            const int r0 = 4 * g;

            int ph[2] = {0, 0};
            int cnt = 0;
            for (int sid = blockIdx.x; sid < NSTR; sid += GRID, ++cnt) {
                const int buf = cnt & 1;
                mbar_wait(FB + 8u * buf, ph[buf]);
                ph[buf] ^= 1;

                const int b  = sid / SPB;
                const int y0 = (sid % SPB) * TY;
                const char* sb = smem + SMOFF + buf * BUFB;
                float4* outb = (float4*)out + (size_t)b * H_ * L4_;

                float4 rA[5], rB[5];
                #pragma unroll
                for (int j = 0; j < 4; ++j) {        // in-rows r0..r0+3
                    const char* rp = sb + (r0 + j) * SROWB + boff;
                    rA[j] = ld_ok ? *(const float4*)rp        : NEG4;
                    rB[j] = ld_ok ? *(const float4*)(rp + 16) : NEG4;
                }
                #pragma unroll
                for (int i = 0; i < 4; ++i) {        // output rows r0+i
                    const char* rp = sb + (r0 + i + 4) * SROWB + boff;
                    rA[(i + 4) % 5] = ld_ok ? *(const float4*)rp        : NEG4;
                    rB[(i + 4) % 5] = ld_ok ? *(const float4*)(rp + 16) : NEG4;

                    const float4 mA = f4max(f4max(f4max(rA[0], rA[1]),
                                                  f4max(rA[2], rA[3])), rA[4]);
                    const float4 mB = f4max(f4max(f4max(rB[0], rB[1]),
                                                  f4max(rB[2], rB[3])), rB[4]);
                    float4 oA, oB;
                    hmax8(mA, mB, oA, oB);

                    if (st_ok) {
                        float4* po = outb + (size_t)(y0 + r0 + i) * L4_;
                        __stcs(po + 2 * o, oA);
                        __stcs(po + 2 * o + 1, oB);
                    }
                }
                mbar_arrive(EB + 8u * buf);
            }
        }
    } else {
        // ---------------- generic fallback (any k), SAME padding ----------------
        const int padL = (k - 1) / 2;
        const int C = 3, W = 384;
        for (int sid = blockIdx.x; sid < NSTR; sid += GRID) {
            const int b  = sid / SPB;
            const int y0 = (sid % SPB) * TY;
            for (int x = t; x < L_; x += NT) {
                const int ww = x / C;
                const int cc = x - ww * C;
                for (int ty = 0; ty < TY; ++ty) {
                    const int oy = y0 + ty;
                    float m = -CUDART_INF_F;
                    for (int ky = 0; ky < k; ky++) {
                        const int gy = oy - padL + ky;
                        if (gy < 0 || gy >= H_) continue;
                        for (int kx = 0; kx < k; kx++) {
                            const int gw = ww - padL + kx;
                            if (gw < 0 || gw >= W) continue;
                            m = fmaxf(m, in[((size_t)b * H_ + gy) * L_ + gw * C + cc]);
                        }
                    }
                    out[((size_t)b * H_ + oy) * L_ + x] = m;
                }
            }
        }
    }
}

extern "C" void kernel_launch(void* const* d_in, const int* in_sizes, int n_in,
                              void* d_out, int out_size)
{
    const float* images = (const float*)d_in[0];
    const int*   kptr   = (const int*)d_in[1];
    float*       out    = (float*)d_out;

    cudaFuncSetAttribute(dilate5_kernel,
                         cudaFuncAttributeMaxDynamicSharedMemorySize, SMEMB);

    dilate5_kernel<<<GRID, NT, SMEMB>>>(images, kptr, out);
}